// round 1
// baseline (speedup 1.0000x reference)
#include <cuda_runtime.h>
#include <cstdint>

// Problem constants
#define M_DIM 4096      // 2*2048 rows of x
#define K_DIM 2048      // in_features
#define N_DIM 8192      // out_features

// NF4 codebook (compile-time __constant__, no runtime copies needed)
__constant__ float c_nf4[16] = {
    -1.0f, -0.6961928009986877f, -0.5250730514526367f, -0.39491748809814453f,
    -0.28444138169288635f, -0.18477343022823334f, -0.09105003625154495f, 0.0f,
    0.07958029955625534f, 0.16093020141124725f, 0.24611230194568634f,
    0.33791524171829224f, 0.44070982933044434f, 0.5626170039176941f,
    0.7229568362236023f, 1.0f
};

// Scratch: dequantized W (tf32-rounded f32, row-major [N,K]) and tf32-rounded x.
__device__ float g_W[(size_t)N_DIM * K_DIM];
__device__ float g_X[(size_t)M_DIM * K_DIM];

// Round-to-nearest tf32 (keeps value in f32 bits; avoids the -2^-10 truncation bias)
__device__ __forceinline__ float to_tf32(float f) {
    uint32_t u;
    asm("cvt.rna.tf32.f32 %0, %1;" : "=r"(u) : "f"(f));
    return __uint_as_float(u);
}

// ---------------------------------------------------------------------------
// Prep kernel 1: dequantize W. 4 codes per thread (same 64-wide scale block).
// ---------------------------------------------------------------------------
__global__ void dequant_w_kernel(const int* __restrict__ q,
                                 const float* __restrict__ scale) {
    size_t i = ((size_t)blockIdx.x * blockDim.x + threadIdx.x) * 4;
    int4 c = *reinterpret_cast<const int4*>(q + i);
    float s = __ldg(scale + (i >> 6));
    float4 w;
    w.x = to_tf32(c_nf4[c.x] * s);
    w.y = to_tf32(c_nf4[c.y] * s);
    w.z = to_tf32(c_nf4[c.z] * s);
    w.w = to_tf32(c_nf4[c.w] * s);
    *reinterpret_cast<float4*>(g_W + i) = w;
}

// ---------------------------------------------------------------------------
// Prep kernel 2: tf32-round x into g_X.
// ---------------------------------------------------------------------------
__global__ void convert_x_kernel(const float* __restrict__ x) {
    size_t i = ((size_t)blockIdx.x * blockDim.x + threadIdx.x) * 4;
    float4 v = *reinterpret_cast<const float4*>(x + i);
    v.x = to_tf32(v.x);
    v.y = to_tf32(v.y);
    v.z = to_tf32(v.z);
    v.w = to_tf32(v.w);
    *reinterpret_cast<float4*>(g_X + i) = v;
}

// ---------------------------------------------------------------------------
// GEMM: out[M,N] = g_X[M,K] * g_W[N,K]^T + bias
// 128x128 block tile, BK=32, double-buffered cp.async, mma.sync m16n8k8 tf32.
// 256 threads = 8 warps in a 2(M) x 4(N) layout; each warp: 64x32 via 4x4 MMAs.
// ---------------------------------------------------------------------------
#define BK 32
#define LDS_STRIDE 36   // 32 + 4 pad -> conflict-free fragment loads

__device__ __forceinline__ void cp_async16(void* smem_ptr, const void* gptr) {
    uint32_t s = (uint32_t)__cvta_generic_to_shared(smem_ptr);
    asm volatile("cp.async.cg.shared.global [%0], [%1], 16;\n" :: "r"(s), "l"(gptr));
}

__device__ __forceinline__ void mma_tf32(float* d, const uint32_t* a, const uint32_t* b) {
    asm volatile(
        "mma.sync.aligned.m16n8k8.row.col.f32.tf32.tf32.f32 "
        "{%0,%1,%2,%3}, {%4,%5,%6,%7}, {%8,%9}, {%0,%1,%2,%3};\n"
        : "+f"(d[0]), "+f"(d[1]), "+f"(d[2]), "+f"(d[3])
        : "r"(a[0]), "r"(a[1]), "r"(a[2]), "r"(a[3]),
          "r"(b[0]), "r"(b[1]));
}

__global__ __launch_bounds__(256, 2)
void gemm_tf32_kernel(const float* __restrict__ bias, float* __restrict__ out) {
    extern __shared__ float smem[];
    // Layout: As[2][128][36], Bs[2][128][36]
    float* As = smem;
    float* Bs = smem + 2 * 128 * LDS_STRIDE;

    const int tid  = threadIdx.x;
    const int lane = tid & 31;
    const int warp = tid >> 5;
    const int gid  = lane >> 2;   // group id (row selector within fragment)
    const int tig  = lane & 3;    // thread-in-group (col selector)
    const int wm   = (warp >> 2) * 64;   // warp M offset within block tile
    const int wn   = (warp & 3) * 32;    // warp N offset within block tile
    const int bm   = blockIdx.y * 128;
    const int bn   = blockIdx.x * 128;

    // Global load mapping: 256 threads, each 4x float4 per (A,B) per tile.
    const int lr = tid >> 3;          // 0..31 (row within 32-row slab)
    const int lc = (tid & 7) * 4;     // 0..28 (float col)
    const float* gA = g_X + (size_t)(bm + lr) * K_DIM + lc;
    const float* gB = g_W + (size_t)(bn + lr) * K_DIM + lc;

    auto load_tile = [&](int buf, int kt) {
        float* as = As + buf * 128 * LDS_STRIDE;
        float* bs = Bs + buf * 128 * LDS_STRIDE;
        const size_t koff = (size_t)kt * BK;
        #pragma unroll
        for (int r = 0; r < 4; r++) {
            cp_async16(&as[(lr + 32 * r) * LDS_STRIDE + lc],
                       gA + (size_t)(32 * r) * K_DIM + koff);
            cp_async16(&bs[(lr + 32 * r) * LDS_STRIDE + lc],
                       gB + (size_t)(32 * r) * K_DIM + koff);
        }
    };

    float acc[4][4][4];
    #pragma unroll
    for (int mi = 0; mi < 4; mi++)
        #pragma unroll
        for (int ni = 0; ni < 4; ni++)
            #pragma unroll
            for (int r = 0; r < 4; r++)
                acc[mi][ni][r] = 0.0f;

    const int NT = K_DIM / BK;   // 64 k-tiles
    load_tile(0, 0);
    asm volatile("cp.async.commit_group;\n");

    int buf = 0;
    for (int kt = 0; kt < NT; kt++) {
        asm volatile("cp.async.wait_group 0;\n");
        __syncthreads();
        if (kt + 1 < NT) {
            load_tile(buf ^ 1, kt + 1);
            asm volatile("cp.async.commit_group;\n");
        }

        const float* as = As + buf * 128 * LDS_STRIDE;
        const float* bs = Bs + buf * 128 * LDS_STRIDE;

        #pragma unroll
        for (int kk = 0; kk < BK; kk += 8) {
            uint32_t a[4][4], b[4][2];
            #pragma unroll
            for (int mi = 0; mi < 4; mi++) {
                const int m0 = wm + mi * 16;
                a[mi][0] = __float_as_uint(as[(m0 + gid    ) * LDS_STRIDE + kk + tig    ]);
                a[mi][1] = __float_as_uint(as[(m0 + gid + 8) * LDS_STRIDE + kk + tig    ]);
                a[mi][2] = __float_as_uint(as[(m0 + gid    ) * LDS_STRIDE + kk + tig + 4]);
                a[mi][3] = __float_as_uint(as[(m0 + gid + 8) * LDS_STRIDE + kk + tig + 4]);
            }
            #pragma unroll
            for (int ni = 0; ni < 4; ni++) {
                const int n0 = wn + ni * 8;
                b[ni][0] = __float_as_uint(bs[(n0 + gid) * LDS_STRIDE + kk + tig    ]);
                b[ni][1] = __float_as_uint(bs[(n0 + gid) * LDS_STRIDE + kk + tig + 4]);
            }
            #pragma unroll
            for (int mi = 0; mi < 4; mi++)
                #pragma unroll
                for (int ni = 0; ni < 4; ni++)
                    mma_tf32(acc[mi][ni], a[mi], b[ni]);
        }
        buf ^= 1;
    }

    // Epilogue: add bias, write f32 output (row-major [M, N])
    #pragma unroll
    for (int mi = 0; mi < 4; mi++) {
        const int m = bm + wm + mi * 16 + gid;
        #pragma unroll
        for (int ni = 0; ni < 4; ni++) {
            const int n = bn + wn + ni * 8 + tig * 2;
            float2 bv = *reinterpret_cast<const float2*>(bias + n);
            float2 v0 = { acc[mi][ni][0] + bv.x, acc[mi][ni][1] + bv.y };
            float2 v1 = { acc[mi][ni][2] + bv.x, acc[mi][ni][3] + bv.y };
            *reinterpret_cast<float2*>(out + (size_t)m * N_DIM + n)       = v0;
            *reinterpret_cast<float2*>(out + (size_t)(m + 8) * N_DIM + n) = v1;
        }
    }
}

// ---------------------------------------------------------------------------
// Launch
// ---------------------------------------------------------------------------
extern "C" void kernel_launch(void* const* d_in, const int* in_sizes, int n_in,
                              void* d_out, int out_size) {
    const float* x     = (const float*)d_in[0];
    const int*   q     = (const int*)d_in[1];
    const float* scale = (const float*)d_in[2];
    const float* bias  = (const float*)d_in[3];
    float*       out   = (float*)d_out;

    // x: 8388608 elems -> /4 per thread /256 per block = 8192 blocks
    convert_x_kernel<<<8192, 256>>>(x);
    // q: 16777216 elems -> 16384 blocks
    dequant_w_kernel<<<16384, 256>>>(q, scale);

    const int smem_bytes = 2 * 2 * 128 * LDS_STRIDE * (int)sizeof(float); // 73728
    cudaFuncSetAttribute(gemm_tf32_kernel,
                         cudaFuncAttributeMaxDynamicSharedMemorySize, smem_bytes);
    dim3 grid(N_DIM / 128, M_DIM / 128);  // (64, 32)
    gemm_tf32_kernel<<<grid, 256, smem_bytes>>>(bias, out);
}

// round 3
// speedup vs baseline: 1.0197x; 1.0197x over previous
#include <cuda_runtime.h>
#include <cstdint>

#define M_DIM 4096
#define K_DIM 2048
#define N_DIM 8192

#define BM 128
#define BN 256
#define BK 32
#define STAGES 3
#define STRIDE 36                      // 32 + 4 pad, conflict-free
#define A_FLOATS (BM * STRIDE)         // 4608
#define B_FLOATS (BN * STRIDE)         // 9216
#define STAGE_FLOATS (A_FLOATS + B_FLOATS)   // 13824 floats = 55296 B
#define SMEM_BYTES (STAGES * STAGE_FLOATS * 4) // 165888

__constant__ float c_nf4[16] = {
    -1.0f, -0.6961928009986877f, -0.5250730514526367f, -0.39491748809814453f,
    -0.28444138169288635f, -0.18477343022823334f, -0.09105003625154495f, 0.0f,
    0.07958029955625534f, 0.16093020141124725f, 0.24611230194568634f,
    0.33791524171829224f, 0.44070982933044434f, 0.5626170039176941f,
    0.7229568362236023f, 1.0f
};

__device__ __align__(1024) float g_W[(size_t)N_DIM * K_DIM];
__device__ __align__(1024) float g_X[(size_t)M_DIM * K_DIM];

__device__ __forceinline__ float to_tf32(float f) {
    uint32_t u;
    asm("cvt.rna.tf32.f32 %0, %1;" : "=r"(u) : "f"(f));
    return __uint_as_float(u);
}

// ---------------------------------------------------------------------------
// Prep kernels
// ---------------------------------------------------------------------------
__global__ void dequant_w_kernel(const int* __restrict__ q,
                                 const float* __restrict__ scale) {
    size_t i = ((size_t)blockIdx.x * blockDim.x + threadIdx.x) * 4;
    int4 c = *reinterpret_cast<const int4*>(q + i);
    float s = __ldg(scale + (i >> 6));
    float4 w;
    w.x = to_tf32(c_nf4[c.x] * s);
    w.y = to_tf32(c_nf4[c.y] * s);
    w.z = to_tf32(c_nf4[c.z] * s);
    w.w = to_tf32(c_nf4[c.w] * s);
    *reinterpret_cast<float4*>(g_W + i) = w;
}

__global__ void convert_x_kernel(const float* __restrict__ x) {
    size_t i = ((size_t)blockIdx.x * blockDim.x + threadIdx.x) * 4;
    float4 v = *reinterpret_cast<const float4*>(x + i);
    v.x = to_tf32(v.x); v.y = to_tf32(v.y);
    v.z = to_tf32(v.z); v.w = to_tf32(v.w);
    *reinterpret_cast<float4*>(g_X + i) = v;
}

// ---------------------------------------------------------------------------
// GEMM: out[M,N] = g_X[M,K] * g_W[N,K]^T + bias
// 128x256 CTA tile, BK=32, 3-stage cp.async, mma.sync m16n8k8 tf32.
// 256 threads = 8 warps (2M x 4N), warp tile 64x64 (4 m-tiles x 8 n-tiles).
// ---------------------------------------------------------------------------
__device__ __forceinline__ void cp_async16(void* smem_ptr, const void* gptr) {
    uint32_t s = (uint32_t)__cvta_generic_to_shared(smem_ptr);
    asm volatile("cp.async.cg.shared.global [%0], [%1], 16;\n" :: "r"(s), "l"(gptr));
}

__device__ __forceinline__ void mma_tf32(float* d, const uint32_t* a, const uint32_t* b) {
    asm volatile(
        "mma.sync.aligned.m16n8k8.row.col.f32.tf32.tf32.f32 "
        "{%0,%1,%2,%3}, {%4,%5,%6,%7}, {%8,%9}, {%0,%1,%2,%3};\n"
        : "+f"(d[0]), "+f"(d[1]), "+f"(d[2]), "+f"(d[3])
        : "r"(a[0]), "r"(a[1]), "r"(a[2]), "r"(a[3]),
          "r"(b[0]), "r"(b[1]));
}

__global__ __launch_bounds__(256, 1)
void gemm_tf32_kernel(const float* __restrict__ bias, float* __restrict__ out) {
    extern __shared__ float smem[];

    const int tid  = threadIdx.x;
    const int lane = tid & 31;
    const int warp = tid >> 5;
    const int gid  = lane >> 2;          // 0..7
    const int tig  = lane & 3;           // 0..3
    const int wm   = (warp >> 2) * 64;   // 0 or 64
    const int wn   = (warp & 3) * 64;    // 0,64,128,192
    const int bm   = blockIdx.y * BM;
    const int bn   = blockIdx.x * BN;

    // Global load mapping: lr row within 32-row slab, lc float col (16B units)
    const int lr = tid >> 3;             // 0..31
    const int lc = (tid & 7) * 4;        // 0,4,...,28
    const float* gA = g_X + (size_t)(bm + lr) * K_DIM + lc;
    const float* gB = g_W + (size_t)(bn + lr) * K_DIM + lc;

    auto load_tile = [&](int buf, int kt) {
        float* s  = smem + buf * STAGE_FLOATS;
        float* as = s;
        float* bs = s + A_FLOATS;
        const size_t koff = (size_t)kt * BK;
        #pragma unroll
        for (int r = 0; r < 4; r++)
            cp_async16(&as[(lr + 32 * r) * STRIDE + lc],
                       gA + (size_t)(32 * r) * K_DIM + koff);
        #pragma unroll
        for (int r = 0; r < 8; r++)
            cp_async16(&bs[(lr + 32 * r) * STRIDE + lc],
                       gB + (size_t)(32 * r) * K_DIM + koff);
    };

    float acc[4][8][4];
    #pragma unroll
    for (int mi = 0; mi < 4; mi++)
        #pragma unroll
        for (int ni = 0; ni < 8; ni++)
            #pragma unroll
            for (int r = 0; r < 4; r++)
                acc[mi][ni][r] = 0.0f;

    const int NT = K_DIM / BK;   // 64

    load_tile(0, 0);
    asm volatile("cp.async.commit_group;\n");
    load_tile(1, 1);
    asm volatile("cp.async.commit_group;\n");

    int buf = 0;
    for (int kt = 0; kt < NT; kt++) {
        asm volatile("cp.async.wait_group 1;\n");
        __syncthreads();

        if (kt + 2 < NT) {
            int nb = buf + 2; if (nb >= STAGES) nb -= STAGES;
            load_tile(nb, kt + 2);
        }
        asm volatile("cp.async.commit_group;\n");

        const float* as = smem + buf * STAGE_FLOATS;
        const float* bs = as + A_FLOATS;

        #pragma unroll
        for (int kk = 0; kk < BK; kk += 8) {
            uint32_t a[4][4], b[8][2];
            #pragma unroll
            for (int mi = 0; mi < 4; mi++) {
                const int m0 = wm + mi * 16;
                a[mi][0] = __float_as_uint(as[(m0 + gid    ) * STRIDE + kk + tig    ]);
                a[mi][1] = __float_as_uint(as[(m0 + gid + 8) * STRIDE + kk + tig    ]);
                a[mi][2] = __float_as_uint(as[(m0 + gid    ) * STRIDE + kk + tig + 4]);
                a[mi][3] = __float_as_uint(as[(m0 + gid + 8) * STRIDE + kk + tig + 4]);
            }
            #pragma unroll
            for (int ni = 0; ni < 8; ni++) {
                const int n0 = wn + ni * 8;
                b[ni][0] = __float_as_uint(bs[(n0 + gid) * STRIDE + kk + tig    ]);
                b[ni][1] = __float_as_uint(bs[(n0 + gid) * STRIDE + kk + tig + 4]);
            }
            #pragma unroll
            for (int mi = 0; mi < 4; mi++)
                #pragma unroll
                for (int ni = 0; ni < 8; ni++)
                    mma_tf32(acc[mi][ni], a[mi], b[ni]);
        }
        buf++; if (buf >= STAGES) buf = 0;
    }

    // Epilogue: bias add, f32 store
    #pragma unroll
    for (int mi = 0; mi < 4; mi++) {
        const int m = bm + wm + mi * 16 + gid;
        #pragma unroll
        for (int ni = 0; ni < 8; ni++) {
            const int n = bn + wn + ni * 8 + tig * 2;
            float2 bv = *reinterpret_cast<const float2*>(bias + n);
            float2 v0 = { acc[mi][ni][0] + bv.x, acc[mi][ni][1] + bv.y };
            float2 v1 = { acc[mi][ni][2] + bv.x, acc[mi][ni][3] + bv.y };
            *reinterpret_cast<float2*>(out + (size_t)m * N_DIM + n)       = v0;
            *reinterpret_cast<float2*>(out + (size_t)(m + 8) * N_DIM + n) = v1;
        }
    }
}

// ---------------------------------------------------------------------------
// Launch
// ---------------------------------------------------------------------------
extern "C" void kernel_launch(void* const* d_in, const int* in_sizes, int n_in,
                              void* d_out, int out_size) {
    const float* x     = (const float*)d_in[0];
    const int*   q     = (const int*)d_in[1];
    const float* scale = (const float*)d_in[2];
    const float* bias  = (const float*)d_in[3];
    float*       out   = (float*)d_out;

    convert_x_kernel<<<8192, 256>>>(x);
    dequant_w_kernel<<<16384, 256>>>(q, scale);

    cudaFuncSetAttribute(gemm_tf32_kernel,
                         cudaFuncAttributeMaxDynamicSharedMemorySize, SMEM_BYTES);
    dim3 grid(N_DIM / BN, M_DIM / BM);   // (32, 32)
    gemm_tf32_kernel<<<grid, 256, SMEM_BYTES>>>(bias, out);
}

// round 4
// speedup vs baseline: 2.1356x; 2.0943x over previous
#include <cuda_runtime.h>
#include <cuda_fp16.h>
#include <cstdint>

#define M_DIM 4096
#define K_DIM 2048
#define N_DIM 8192

#define BM 128
#define BN 256
#define BKH 64                      // halfs per k-tile (128 B per row)
#define STAGES 4
#define NT (K_DIM / BKH)            // 32 k-tiles

#define A_CHUNKS (BM * 8)           // 16B chunks per A tile (1024)
#define B_CHUNKS (BN * 8)           // 2048
#define STAGE_BYTES ((A_CHUNKS + B_CHUNKS) * 16)   // 49152
#define SMEM_BYTES (STAGES * STAGE_BYTES)          // 196608

__constant__ float c_nf4[16] = {
    -1.0f, -0.6961928009986877f, -0.5250730514526367f, -0.39491748809814453f,
    -0.28444138169288635f, -0.18477343022823334f, -0.09105003625154495f, 0.0f,
    0.07958029955625534f, 0.16093020141124725f, 0.24611230194568634f,
    0.33791524171829224f, 0.44070982933044434f, 0.5626170039176941f,
    0.7229568362236023f, 1.0f
};

__device__ __align__(1024) __half g_W[(size_t)N_DIM * K_DIM];
__device__ __align__(1024) __half g_X[(size_t)M_DIM * K_DIM];

// ---------------------------------------------------------------------------
// Prep kernels: fp16 conversion (fp16 mantissa == tf32 mantissa: 10 bits)
// ---------------------------------------------------------------------------
__global__ void dequant_w_kernel(const int* __restrict__ q,
                                 const float* __restrict__ scale) {
    size_t i = ((size_t)blockIdx.x * blockDim.x + threadIdx.x) * 4;
    int4 c = *reinterpret_cast<const int4*>(q + i);
    float s = __ldg(scale + (i >> 6));
    __half2 lo = __floats2half2_rn(c_nf4[c.x] * s, c_nf4[c.y] * s);
    __half2 hi = __floats2half2_rn(c_nf4[c.z] * s, c_nf4[c.w] * s);
    uint2 v = { *reinterpret_cast<uint32_t*>(&lo), *reinterpret_cast<uint32_t*>(&hi) };
    *reinterpret_cast<uint2*>(g_W + i) = v;
}

__global__ void convert_x_kernel(const float* __restrict__ x) {
    size_t i = ((size_t)blockIdx.x * blockDim.x + threadIdx.x) * 4;
    float4 f = *reinterpret_cast<const float4*>(x + i);
    __half2 lo = __floats2half2_rn(f.x, f.y);
    __half2 hi = __floats2half2_rn(f.z, f.w);
    uint2 v = { *reinterpret_cast<uint32_t*>(&lo), *reinterpret_cast<uint32_t*>(&hi) };
    *reinterpret_cast<uint2*>(g_X + i) = v;
}

// ---------------------------------------------------------------------------
// GEMM: out[M,N] = g_X[M,K] * g_W[N,K]^T + bias   (fp16 in, fp32 accumulate)
// 128x256 CTA tile, BK=64 halfs, 4-stage cp.async, ldmatrix.x4 fragments,
// XOR-swizzled smem (16B chunks), mma.sync.m16n8k16.f16.
// 8 warps (2M x 4N), warp tile 64x64: per k16 slice 4 A-ldsm + 4 B-ldsm + 32 MMA.
// ---------------------------------------------------------------------------
__device__ __forceinline__ void cp_async16(uint32_t saddr, const void* gptr) {
    asm volatile("cp.async.cg.shared.global [%0], [%1], 16;\n" :: "r"(saddr), "l"(gptr));
}

__device__ __forceinline__ void ldsm_x4(uint32_t& r0, uint32_t& r1,
                                        uint32_t& r2, uint32_t& r3, uint32_t addr) {
    asm volatile("ldmatrix.sync.aligned.m8n8.x4.shared.b16 {%0,%1,%2,%3}, [%4];"
                 : "=r"(r0), "=r"(r1), "=r"(r2), "=r"(r3) : "r"(addr));
}

__device__ __forceinline__ void mma_f16(float* d, const uint32_t* a, const uint32_t* b) {
    asm volatile(
        "mma.sync.aligned.m16n8k16.row.col.f32.f16.f16.f32 "
        "{%0,%1,%2,%3}, {%4,%5,%6,%7}, {%8,%9}, {%0,%1,%2,%3};\n"
        : "+f"(d[0]), "+f"(d[1]), "+f"(d[2]), "+f"(d[3])
        : "r"(a[0]), "r"(a[1]), "r"(a[2]), "r"(a[3]), "r"(b[0]), "r"(b[1]));
}

__global__ __launch_bounds__(256, 1)
void gemm_f16_kernel(const float* __restrict__ bias, float* __restrict__ out) {
    extern __shared__ char smem[];
    const uint32_t sb = (uint32_t)__cvta_generic_to_shared(smem);

    const int tid  = threadIdx.x;
    const int lane = tid & 31;
    const int warp = tid >> 5;
    const int gid  = lane >> 2;
    const int tig  = lane & 3;
    const int wm   = (warp >> 2) * 64;
    const int wn   = (warp & 3) * 64;
    const int bm   = blockIdx.y * BM;
    const int bn   = blockIdx.x * BN;

    const __half* gA = g_X + (size_t)bm * K_DIM;
    const __half* gB = g_W + (size_t)bn * K_DIM;

    // cp.async mapping: chunk idx -> (row, col-chunk), XOR swizzle on write
    auto load_tile = [&](int buf, int kt) {
        const uint32_t s = sb + buf * STAGE_BYTES;
        const int koff = kt * BKH;
        #pragma unroll
        for (int it = 0; it < 4; it++) {
            int idx = tid + it * 256;            // 0..1023
            int r = idx >> 3, c = idx & 7;
            cp_async16(s + (r * 8 + ((r & 7) ^ c)) * 16,
                       gA + (size_t)r * K_DIM + koff + c * 8);
        }
        const uint32_t sB = s + A_CHUNKS * 16;
        #pragma unroll
        for (int it = 0; it < 8; it++) {
            int idx = tid + it * 256;            // 0..2047
            int r = idx >> 3, c = idx & 7;
            cp_async16(sB + (r * 8 + ((r & 7) ^ c)) * 16,
                       gB + (size_t)r * K_DIM + koff + c * 8);
        }
    };

    float acc[4][8][4];
    #pragma unroll
    for (int mi = 0; mi < 4; mi++)
        #pragma unroll
        for (int ni = 0; ni < 8; ni++)
            #pragma unroll
            for (int r = 0; r < 4; r++)
                acc[mi][ni][r] = 0.0f;

    // Per-lane ldmatrix row/col precompute (row part is k-slice invariant)
    // A: rows wm + mi*16 + (lane&15); col-chunk = 2*ks + (lane>>4)
    const int a_row_off = lane & 15;
    const int a_hi      = lane >> 4;           // 0 or 1
    // B: rows wn + p*16 + (lane&7) + ((lane>>4)*8); col-chunk = 2*ks + ((lane>>3)&1)
    const int b_row_off = (lane & 7) + ((lane >> 4) << 3);
    const int b_hi      = (lane >> 3) & 1;

    load_tile(0, 0); asm volatile("cp.async.commit_group;\n");
    load_tile(1, 1); asm volatile("cp.async.commit_group;\n");
    load_tile(2, 2); asm volatile("cp.async.commit_group;\n");

    for (int kt = 0; kt < NT; kt++) {
        asm volatile("cp.async.wait_group 2;\n");
        __syncthreads();

        if (kt + 3 < NT) load_tile((kt + 3) & 3, kt + 3);
        asm volatile("cp.async.commit_group;\n");

        const uint32_t sA = sb + (kt & 3) * STAGE_BYTES;
        const uint32_t sB = sA + A_CHUNKS * 16;

        #pragma unroll
        for (int ks = 0; ks < 4; ks++) {
            const int c0 = 2 * ks;
            uint32_t a[4][4], b[4][4];
            #pragma unroll
            for (int mi = 0; mi < 4; mi++) {
                const int row = wm + mi * 16 + a_row_off;
                const uint32_t addr = sA + (row * 8 + ((row & 7) ^ (c0 + a_hi))) * 16;
                ldsm_x4(a[mi][0], a[mi][1], a[mi][2], a[mi][3], addr);
            }
            #pragma unroll
            for (int p = 0; p < 4; p++) {
                const int row = wn + p * 16 + b_row_off;
                const uint32_t addr = sB + (row * 8 + ((row & 7) ^ (c0 + b_hi))) * 16;
                ldsm_x4(b[p][0], b[p][1], b[p][2], b[p][3], addr);
            }
            #pragma unroll
            for (int mi = 0; mi < 4; mi++)
                #pragma unroll
                for (int p = 0; p < 4; p++) {
                    mma_f16(acc[mi][2 * p],     a[mi], &b[p][0]);
                    mma_f16(acc[mi][2 * p + 1], a[mi], &b[p][2]);
                }
        }
    }

    // Epilogue
    #pragma unroll
    for (int mi = 0; mi < 4; mi++) {
        const int m = bm + wm + mi * 16 + gid;
        #pragma unroll
        for (int ni = 0; ni < 8; ni++) {
            const int n = bn + wn + ni * 8 + tig * 2;
            float2 bv = *reinterpret_cast<const float2*>(bias + n);
            float2 v0 = { acc[mi][ni][0] + bv.x, acc[mi][ni][1] + bv.y };
            float2 v1 = { acc[mi][ni][2] + bv.x, acc[mi][ni][3] + bv.y };
            *reinterpret_cast<float2*>(out + (size_t)m * N_DIM + n)       = v0;
            *reinterpret_cast<float2*>(out + (size_t)(m + 8) * N_DIM + n) = v1;
        }
    }
}

// ---------------------------------------------------------------------------
// Launch
// ---------------------------------------------------------------------------
extern "C" void kernel_launch(void* const* d_in, const int* in_sizes, int n_in,
                              void* d_out, int out_size) {
    const float* x     = (const float*)d_in[0];
    const int*   q     = (const int*)d_in[1];
    const float* scale = (const float*)d_in[2];
    const float* bias  = (const float*)d_in[3];
    float*       out   = (float*)d_out;

    convert_x_kernel<<<8192, 256>>>(x);
    dequant_w_kernel<<<16384, 256>>>(q, scale);

    cudaFuncSetAttribute(gemm_f16_kernel,
                         cudaFuncAttributeMaxDynamicSharedMemorySize, SMEM_BYTES);
    dim3 grid(N_DIM / BN, M_DIM / BM);   // (32, 32)
    gemm_f16_kernel<<<grid, 256, SMEM_BYTES>>>(bias, out);
}